// round 1
// baseline (speedup 1.0000x reference)
#include <cuda_runtime.h>
#include <cuda_bf16.h>
#include <math.h>

// ---------------------------------------------------------------------------
// Frequency-domain partitioned convolution (uniform overlap-save).
//   T = 441000 samples, B = 32 batches, L = 44100 taps.
//   Partition P = 8192, FFT N = 16384, IR partitions NPART = 6.
//   Batch pairing: z = x[2p] + i*x[2p+1]; ifft(H*Z) = conv(x[2p]) + i*conv(x[2p+1]).
//   Forward radix-4 DIF (digit-reversed output) -> elementwise multiply in the
//   permuted domain (H stored in the same order) -> exact stage-inverse DIT.
//   Scale 1/N folded into H.
// ---------------------------------------------------------------------------

#define T_LEN   441000
#define BATCH   32
#define PAIRS   16
#define IR_LEN  44100
#define P_HOP   8192
#define NFFT    16384
#define NBLK    54          // ceil(441000 / 8192)
#define NPART   6           // ceil(44100 / 8192)
#define NTHREADS 512

// Device-global scratch (allocation-free rule: static __device__ arrays)
__device__ float2 g_tw[NFFT];                  // 128 KB twiddle table
__device__ float2 g_H[NPART][NFFT];            // 768 KB IR partition spectra
__device__ float2 g_Z[PAIRS][NBLK][NFFT];      // ~113 MB input block spectra

// ---------------- complex helpers ----------------
__device__ __forceinline__ float2 cadd(float2 a, float2 b) { return make_float2(a.x + b.x, a.y + b.y); }
__device__ __forceinline__ float2 csub(float2 a, float2 b) { return make_float2(a.x - b.x, a.y - b.y); }
__device__ __forceinline__ float2 cmul(float2 a, float2 b) {
    return make_float2(fmaf(a.x, b.x, -a.y * b.y), fmaf(a.x, b.y, a.y * b.x));
}
// a * conj(b)
__device__ __forceinline__ float2 cmulc(float2 a, float2 b) {
    return make_float2(fmaf(a.x, b.x, a.y * b.y), fmaf(a.y, b.x, -a.x * b.y));
}

// ---------------- in-smem 16384-pt complex FFT, radix-4 ----------------
// Forward DIF: natural input -> digit-reversed output.
__device__ void fft_fwd(float2* sm, int tid) {
    #pragma unroll
    for (int s = 0; s < 7; ++s) {
        const int lm  = 12 - 2 * s;      // log2(m)
        const int m   = 1 << lm;
        const int tws = 1 << (2 * s);    // twiddle stride = NFFT / ncur
        #pragma unroll
        for (int b = tid; b < NFFT / 4; b += NTHREADS) {
            const int j  = b & (m - 1);
            const int i0 = ((b >> lm) << (lm + 2)) + j;
            float2 a  = sm[i0];
            float2 bb = sm[i0 + m];
            float2 c  = sm[i0 + 2 * m];
            float2 d  = sm[i0 + 3 * m];
            float2 u0 = cadd(a, c);
            float2 u1 = csub(a, c);
            float2 u2 = cadd(bb, d);
            float2 t  = csub(bb, d);
            float2 u3 = make_float2(t.y, -t.x);   // -i*(b-d)
            const int k1 = j * tws;
            float2 w1 = g_tw[k1];
            float2 w2 = g_tw[2 * k1];
            float2 w3 = g_tw[3 * k1];
            sm[i0]         = cadd(u0, u2);
            sm[i0 + m]     = cmul(cadd(u1, u3), w1);
            sm[i0 + 2 * m] = cmul(csub(u0, u2), w2);
            sm[i0 + 3 * m] = cmul(csub(u1, u3), w3);
        }
        __syncthreads();
    }
}

// Exact inverse: digit-reversed input -> natural output, result = NFFT * ifft.
__device__ void fft_inv(float2* sm, int tid) {
    #pragma unroll
    for (int s = 6; s >= 0; --s) {
        const int lm  = 12 - 2 * s;
        const int m   = 1 << lm;
        const int tws = 1 << (2 * s);
        #pragma unroll
        for (int b = tid; b < NFFT / 4; b += NTHREADS) {
            const int j  = b & (m - 1);
            const int i0 = ((b >> lm) << (lm + 2)) + j;
            const int k1 = j * tws;
            float2 w1 = g_tw[k1];
            float2 w2 = g_tw[2 * k1];
            float2 w3 = g_tw[3 * k1];
            float2 y0 = sm[i0];
            float2 y1 = cmulc(sm[i0 + m],     w1);
            float2 y2 = cmulc(sm[i0 + 2 * m], w2);
            float2 y3 = cmulc(sm[i0 + 3 * m], w3);
            float2 v0 = cadd(y0, y2);
            float2 v2 = csub(y0, y2);
            float2 v1 = cadd(y1, y3);
            float2 v3 = csub(y1, y3);
            float2 iv3 = make_float2(-v3.y, v3.x);  // i*v3
            sm[i0]         = cadd(v0, v1);
            sm[i0 + 2 * m] = csub(v0, v1);
            sm[i0 + m]     = cadd(v2, iv3);
            sm[i0 + 3 * m] = csub(v2, iv3);
        }
        __syncthreads();
    }
}

// ---------------- kernels ----------------
__global__ void twiddle_kernel() {
    int k = blockIdx.x * blockDim.x + threadIdx.x;
    if (k < NFFT) {
        double ang = -2.0 * 3.14159265358979323846 * (double)k / (double)NFFT;
        g_tw[k] = make_float2((float)cos(ang), (float)sin(ang));
    }
}

__global__ void h_kernel(const float* __restrict__ ir) {
    extern __shared__ float2 sm[];
    const int c   = blockIdx.x;
    const int tid = threadIdx.x;
    for (int k = tid; k < NFFT; k += NTHREADS) {
        const int tap = c * P_HOP + k;
        float v = (k < P_HOP && tap < IR_LEN) ? ir[tap] : 0.0f;
        sm[k] = make_float2(v, 0.0f);
    }
    __syncthreads();
    fft_fwd(sm, tid);
    const float inv = 1.0f / (float)NFFT;   // fold 1/N normalization into H
    for (int k = tid; k < NFFT; k += NTHREADS) {
        float2 v = sm[k];
        g_H[c][k] = make_float2(v.x * inv, v.y * inv);
    }
}

__global__ void z_kernel(const float* __restrict__ x) {
    extern __shared__ float2 sm[];
    const int d   = blockIdx.x;     // input block index
    const int p   = blockIdx.y;     // batch pair
    const int tid = threadIdx.x;
    const int base = d * P_HOP - P_HOP;     // block covers [ (d-1)P, (d+1)P )
    const float* xe = x + (2 * p)     * T_LEN;
    const float* xo = x + (2 * p + 1) * T_LEN;
    for (int k = tid; k < NFFT; k += NTHREADS) {
        const int idx = base + k;
        float re = 0.0f, im = 0.0f;
        if (idx >= 0 && idx < T_LEN) { re = xe[idx]; im = xo[idx]; }
        sm[k] = make_float2(re, im);
    }
    __syncthreads();
    fft_fwd(sm, tid);
    float2* __restrict__ zdst = g_Z[p][d];
    for (int k = tid; k < NFFT; k += NTHREADS) zdst[k] = sm[k];
}

__global__ void y_kernel(const float* __restrict__ x,
                         const float* __restrict__ wet_param,
                         float* __restrict__ out) {
    extern __shared__ float2 sm[];
    const int m   = blockIdx.x;     // output block index
    const int p   = blockIdx.y;     // batch pair
    const int tid = threadIdx.x;

    // Spectral MAC over IR partitions (all arrays share the same digit-reversed order)
    for (int k = tid; k < NFFT; k += NTHREADS) {
        float2 acc = make_float2(0.0f, 0.0f);
        #pragma unroll
        for (int c = 0; c < NPART; ++c) {
            if (c <= m) {
                acc = cadd(acc, cmul(g_H[c][k], g_Z[p][m - c][k]));
            }
        }
        sm[k] = acc;
    }
    __syncthreads();
    fft_inv(sm, tid);

    const float wet = 1.0f / (1.0f + __expf(-wet_param[0]));
    const float dry = 1.0f - wet;
    const float* xe = x + (2 * p)     * T_LEN;
    const float* xo = x + (2 * p + 1) * T_LEN;
    float* oe = out + (2 * p)     * T_LEN;
    float* oo = out + (2 * p + 1) * T_LEN;

    // valid overlap-save outputs: positions [P, 2P) -> samples [mP, (m+1)P)
    for (int loc = tid; loc < P_HOP; loc += NTHREADS) {
        const int n = m * P_HOP + loc;
        if (n < T_LEN) {
            float2 yv = sm[P_HOP + loc];
            oe[n] = dry * xe[n] + wet * yv.x;
            oo[n] = dry * xo[n] + wet * yv.y;
        }
    }
}

// ---------------- launcher ----------------
extern "C" void kernel_launch(void* const* d_in, const int* in_sizes, int n_in,
                              void* d_out, int out_size) {
    const float* x  = (const float*)d_in[0];
    const float* ir = (const float*)d_in[1];
    const float* wp = (const float*)d_in[2];
    float* out = (float*)d_out;

    const int smem = NFFT * sizeof(float2);   // 128 KB dynamic smem
    cudaFuncSetAttribute(h_kernel, cudaFuncAttributeMaxDynamicSharedMemorySize, smem);
    cudaFuncSetAttribute(z_kernel, cudaFuncAttributeMaxDynamicSharedMemorySize, smem);
    cudaFuncSetAttribute(y_kernel, cudaFuncAttributeMaxDynamicSharedMemorySize, smem);

    twiddle_kernel<<<(NFFT + 1023) / 1024, 1024>>>();
    h_kernel<<<NPART, NTHREADS, smem>>>(ir);
    z_kernel<<<dim3(NBLK, PAIRS), NTHREADS, smem>>>(x);
    y_kernel<<<dim3(NBLK, PAIRS), NTHREADS, smem>>>(x, wp, out);
}

// round 3
// speedup vs baseline: 1.3393x; 1.3393x over previous
#include <cuda_runtime.h>
#include <math.h>

// ---------------------------------------------------------------------------
// Frequency-domain partitioned convolution (uniform overlap-save), v2.
//   Register-staged radix-16 FFT passes: 16 float2 per thread, two radix-4
//   stages per smem round trip. 1024 threads/CTA. Padded smem (i + i/16).
//   Forward DIF leaves digit-reversed order; H stored in same order; exact
//   algebraic inverse (DIT, conj twiddles); 1/N folded into H.
// ---------------------------------------------------------------------------

#define T_LEN   441000
#define PAIRS   16
#define IR_LEN  44100
#define P_HOP   8192
#define NFFT    16384
#define NBLK    54          // ceil(441000 / 8192)
#define NPART   6           // ceil(44100 / 8192)
#define NT      1024

__device__ __align__(16) float2 g_tw[NFFT];
__device__ __align__(16) float2 g_H[NPART][NFFT];
__device__ __align__(16) float2 g_Z[PAIRS][NBLK][NFFT];

__device__ __forceinline__ int PADi(int i) { return i + (i >> 4); }
#define SMEM_F2 (NFFT + (NFFT >> 4))        // padded float2 count

// ---------------- complex helpers ----------------
__device__ __forceinline__ float2 cadd(float2 a, float2 b) { return make_float2(a.x + b.x, a.y + b.y); }
__device__ __forceinline__ float2 csub(float2 a, float2 b) { return make_float2(a.x - b.x, a.y - b.y); }
__device__ __forceinline__ float2 cmul(float2 a, float2 b) {
    return make_float2(fmaf(a.x, b.x, -a.y * b.y), fmaf(a.x, b.y, a.y * b.x));
}
// a * conj(b)
__device__ __forceinline__ float2 cmulc(float2 a, float2 b) {
    return make_float2(fmaf(a.x, b.x, a.y * b.y), fmaf(a.y, b.x, -a.x * b.y));
}

// ---------------- radix-4 butterflies ----------------
// Forward DIF with twiddles (a' at base, outputs b',c',d' get w1,w2,w3)
__device__ __forceinline__ void bfly_fwd_w(float2& a, float2& b, float2& c, float2& d,
                                           float2 w1, float2 w2, float2 w3) {
    float2 u0 = cadd(a, c), u1 = csub(a, c), u2 = cadd(b, d), t = csub(b, d);
    float2 u3 = make_float2(t.y, -t.x);   // -i*(b-d)
    a = cadd(u0, u2);
    b = cmul(cadd(u1, u3), w1);
    c = cmul(csub(u0, u2), w2);
    d = cmul(csub(u1, u3), w3);
}
__device__ __forceinline__ void bfly_fwd_k(float2& a, float2& b, float2& c, float2& d, int k1) {
    float2 w1 = __ldg(&g_tw[k1]);
    float2 w2 = __ldg(&g_tw[2 * k1]);
    float2 w3 = __ldg(&g_tw[3 * k1]);
    bfly_fwd_w(a, b, c, d, w1, w2, w3);
}
// Forward DIF, unity twiddles (last stage)
__device__ __forceinline__ void bfly_fwd_nw(float2& a, float2& b, float2& c, float2& d) {
    float2 u0 = cadd(a, c), u1 = csub(a, c), u2 = cadd(b, d), t = csub(b, d);
    float2 u3 = make_float2(t.y, -t.x);
    a = cadd(u0, u2); b = cadd(u1, u3); c = csub(u0, u2); d = csub(u1, u3);
}
// Inverse DIT with conj twiddles
__device__ __forceinline__ void bfly_inv_w(float2& a, float2& b, float2& c, float2& d,
                                           float2 w1, float2 w2, float2 w3) {
    float2 y0 = a, y1 = cmulc(b, w1), y2 = cmulc(c, w2), y3 = cmulc(d, w3);
    float2 v0 = cadd(y0, y2), v2 = csub(y0, y2);
    float2 v1 = cadd(y1, y3), v3 = csub(y1, y3);
    float2 iv3 = make_float2(-v3.y, v3.x);  // i*v3
    a = cadd(v0, v1); b = cadd(v2, iv3); c = csub(v0, v1); d = csub(v2, iv3);
}
__device__ __forceinline__ void bfly_inv_k(float2& a, float2& b, float2& c, float2& d, int k1) {
    float2 w1 = __ldg(&g_tw[k1]);
    float2 w2 = __ldg(&g_tw[2 * k1]);
    float2 w3 = __ldg(&g_tw[3 * k1]);
    bfly_inv_w(a, b, c, d, w1, w2, w3);
}
// Inverse DIT, unity twiddles (stage 6)
__device__ __forceinline__ void bfly_inv_nw(float2& a, float2& b, float2& c, float2& d) {
    float2 v0 = cadd(a, c), v2 = csub(a, c);
    float2 v1 = cadd(b, d), v3 = csub(b, d);
    float2 iv3 = make_float2(-v3.y, v3.x);
    a = cadd(v0, v1); b = cadd(v2, iv3); c = csub(v0, v1); d = csub(v2, iv3);
}

// ---------------- register pass: stages S and S+1 (forward) ----------------
// Thread t owns v[j] = element base + j*mq, mq = m/4, m = 4^(6-S).
// base = (t >> (10-2S)) << (14-2S)  |  (t & (mq-1)).
template<int S>
__device__ __forceinline__ void fwd_bflys(float2 v[16], int r, int mq, int tws) {
    #pragma unroll
    for (int j1 = 0; j1 < 4; ++j1) {
        int k1 = (r + j1 * mq) * tws;
        bfly_fwd_k(v[j1], v[j1 + 4], v[j1 + 8], v[j1 + 12], k1);
    }
    int k1 = r * (tws << 2);
    float2 w1 = __ldg(&g_tw[k1]);
    float2 w2 = __ldg(&g_tw[2 * k1]);
    float2 w3 = __ldg(&g_tw[3 * k1]);
    #pragma unroll
    for (int q = 0; q < 4; ++q)
        bfly_fwd_w(v[4 * q], v[4 * q + 1], v[4 * q + 2], v[4 * q + 3], w1, w2, w3);
}

template<int S>
__device__ __forceinline__ void fwd_mid_pass(float2* sm, int t) {
    const int m   = 1 << (12 - 2 * S);
    const int mq  = m >> 2;
    const int tws = 1 << (2 * S);
    const int r    = t & (mq - 1);
    const int base = ((t >> (10 - 2 * S)) << (14 - 2 * S)) + r;
    float2 v[16];
    #pragma unroll
    for (int j = 0; j < 16; ++j) v[j] = sm[PADi(base + j * mq)];
    fwd_bflys<S>(v, r, mq, tws);
    #pragma unroll
    for (int j = 0; j < 16; ++j) sm[PADi(base + j * mq)] = v[j];
}

// Forward stages 0+1 from registers (input loaded by caller, natural order:
// v[j] = element t + 1024*j), then store to smem.
__device__ __forceinline__ void fwd_pass0_store(float2* sm, int t, float2 v[16]) {
    fwd_bflys<0>(v, t, 1024, 1);
    #pragma unroll
    for (int j = 0; j < 16; ++j) sm[PADi(t + j * 1024)] = v[j];
}

// Forward stage 6 (unity twiddles, contiguous quads) + store to global (scaled).
__device__ __forceinline__ void fwd_stage6_store(const float2* sm, int t,
                                                 float2* __restrict__ dst, float s) {
    float4* dst4 = (float4*)dst;
    #pragma unroll
    for (int u = 0; u < 4; ++u) {
        int a = 4 * t + 4096 * u;
        float2 va = sm[PADi(a)], vb = sm[PADi(a + 1)];
        float2 vc = sm[PADi(a + 2)], vd = sm[PADi(a + 3)];
        bfly_fwd_nw(va, vb, vc, vd);
        dst4[(a >> 1)]     = make_float4(va.x * s, va.y * s, vb.x * s, vb.y * s);
        dst4[(a >> 1) + 1] = make_float4(vc.x * s, vc.y * s, vd.x * s, vd.y * s);
    }
}

// Inverse stage 6 (first inverse stage), smem -> smem.
__device__ __forceinline__ void inv_stage6(float2* sm, int t) {
    #pragma unroll
    for (int u = 0; u < 4; ++u) {
        int a = 4 * t + 4096 * u;
        float2 va = sm[PADi(a)], vb = sm[PADi(a + 1)];
        float2 vc = sm[PADi(a + 2)], vd = sm[PADi(a + 3)];
        bfly_inv_nw(va, vb, vc, vd);
        sm[PADi(a)] = va; sm[PADi(a + 1)] = vb;
        sm[PADi(a + 2)] = vc; sm[PADi(a + 3)] = vd;
    }
}

// Inverse pass: stage S+1 then stage S (register-staged), smem -> smem.
template<int S>
__device__ __forceinline__ void inv_bflys(float2 v[16], int r, int mq, int tws) {
    int k1 = r * (tws << 2);
    float2 w1 = __ldg(&g_tw[k1]);
    float2 w2 = __ldg(&g_tw[2 * k1]);
    float2 w3 = __ldg(&g_tw[3 * k1]);
    #pragma unroll
    for (int q = 0; q < 4; ++q)
        bfly_inv_w(v[4 * q], v[4 * q + 1], v[4 * q + 2], v[4 * q + 3], w1, w2, w3);
    #pragma unroll
    for (int j1 = 0; j1 < 4; ++j1) {
        int kk = (r + j1 * mq) * tws;
        bfly_inv_k(v[j1], v[j1 + 4], v[j1 + 8], v[j1 + 12], kk);
    }
}

template<int S>
__device__ __forceinline__ void inv_mid_pass(float2* sm, int t) {
    const int m   = 1 << (12 - 2 * S);
    const int mq  = m >> 2;
    const int tws = 1 << (2 * S);
    const int r    = t & (mq - 1);
    const int base = ((t >> (10 - 2 * S)) << (14 - 2 * S)) + r;
    float2 v[16];
    #pragma unroll
    for (int j = 0; j < 16; ++j) v[j] = sm[PADi(base + j * mq)];
    inv_bflys<S>(v, r, mq, tws);
    #pragma unroll
    for (int j = 0; j < 16; ++j) sm[PADi(base + j * mq)] = v[j];
}

// ---------------- kernels ----------------
__global__ void __launch_bounds__(NT, 1) twiddle_kernel() {
    int k = blockIdx.x * blockDim.x + threadIdx.x;
    if (k < NFFT) {
        double ang = -2.0 * 3.14159265358979323846 * (double)k / (double)NFFT;
        g_tw[k] = make_float2((float)cos(ang), (float)sin(ang));
    }
}

__global__ void __launch_bounds__(NT, 1) h_kernel(const float* __restrict__ ir) {
    extern __shared__ float2 sm[];
    const int c   = blockIdx.x;
    const int t   = threadIdx.x;
    float2 v[16];
    #pragma unroll
    for (int j = 0; j < 16; ++j) {
        int k = t + 1024 * j;
        int tap = c * P_HOP + k;
        float val = (k < P_HOP && tap < IR_LEN) ? ir[tap] : 0.0f;
        v[j] = make_float2(val, 0.0f);
    }
    fwd_pass0_store(sm, t, v);
    __syncthreads();
    fwd_mid_pass<2>(sm, t);
    __syncthreads();
    fwd_mid_pass<4>(sm, t);
    __syncthreads();
    fwd_stage6_store(sm, t, g_H[c], 1.0f / (float)NFFT);
}

__global__ void __launch_bounds__(NT, 1) z_kernel(const float* __restrict__ x) {
    extern __shared__ float2 sm[];
    const int d = blockIdx.x;     // input block index
    const int p = blockIdx.y;     // batch pair
    const int t = threadIdx.x;
    const int base = d * P_HOP - P_HOP;   // covers [(d-1)P, (d+1)P)
    const float* xe = x + (2 * p)     * T_LEN;
    const float* xo = x + (2 * p + 1) * T_LEN;
    float2 v[16];
    #pragma unroll
    for (int j = 0; j < 16; ++j) {
        int idx = base + t + 1024 * j;
        float re = 0.0f, im = 0.0f;
        if (idx >= 0 && idx < T_LEN) { re = xe[idx]; im = xo[idx]; }
        v[j] = make_float2(re, im);
    }
    fwd_pass0_store(sm, t, v);
    __syncthreads();
    fwd_mid_pass<2>(sm, t);
    __syncthreads();
    fwd_mid_pass<4>(sm, t);
    __syncthreads();
    fwd_stage6_store(sm, t, g_Z[p][d], 1.0f);
}

__global__ void __launch_bounds__(NT, 1) y_kernel(const float* __restrict__ x,
                                                  const float* __restrict__ wet_param,
                                                  float* __restrict__ out) {
    extern __shared__ float2 sm[];
    const int mBlk = blockIdx.x;  // output block index
    const int p    = blockIdx.y;  // batch pair
    const int t    = threadIdx.x;

    // Spectral MAC (digit-reversed domain; elementwise => order-invariant).
    // float4 = two complex bins at a time.
    #pragma unroll
    for (int j = 0; j < 8; ++j) {
        int kq = t + 1024 * j;              // float4 index -> complex 2kq, 2kq+1
        float2 a0 = make_float2(0.0f, 0.0f);
        float2 a1 = make_float2(0.0f, 0.0f);
        #pragma unroll
        for (int c = 0; c < NPART; ++c) {
            if (c <= mBlk) {
                float4 h = __ldg((const float4*)g_H[c] + kq);
                float4 z = __ldg((const float4*)g_Z[p][mBlk - c] + kq);
                a0 = cadd(a0, cmul(make_float2(h.x, h.y), make_float2(z.x, z.y)));
                a1 = cadd(a1, cmul(make_float2(h.z, h.w), make_float2(z.z, z.w)));
            }
        }
        sm[PADi(2 * kq)]     = a0;
        sm[PADi(2 * kq + 1)] = a1;
    }
    __syncthreads();

    inv_stage6(sm, t);
    __syncthreads();
    inv_mid_pass<4>(sm, t);     // stages 5 then 4
    __syncthreads();
    inv_mid_pass<2>(sm, t);     // stages 3 then 2
    __syncthreads();

    // Final inverse pass: stages 1 then 0 in registers, then write output mix.
    float2 v[16];
    #pragma unroll
    for (int j = 0; j < 16; ++j) v[j] = sm[PADi(t + 1024 * j)];
    inv_bflys<0>(v, t, 1024, 1);

    const float wet = 1.0f / (1.0f + __expf(-wet_param[0]));
    const float dry = 1.0f - wet;
    const float* xe = x + (2 * p)     * T_LEN;
    const float* xo = x + (2 * p + 1) * T_LEN;
    float* oe = out + (2 * p)     * T_LEN;
    float* oo = out + (2 * p + 1) * T_LEN;

    // valid overlap-save outputs at natural positions [P, 2P) = j in [8,16)
    #pragma unroll
    for (int j = 8; j < 16; ++j) {
        int n = mBlk * P_HOP + t + 1024 * j - P_HOP;
        if (n < T_LEN) {
            oe[n] = fmaf(dry, xe[n], wet * v[j].x);
            oo[n] = fmaf(dry, xo[n], wet * v[j].y);
        }
    }
}

// ---------------- launcher ----------------
extern "C" void kernel_launch(void* const* d_in, const int* in_sizes, int n_in,
                              void* d_out, int out_size) {
    const float* x  = (const float*)d_in[0];
    const float* ir = (const float*)d_in[1];
    const float* wp = (const float*)d_in[2];
    float* out = (float*)d_out;

    const int smem = SMEM_F2 * sizeof(float2);   // 139264 B
    cudaFuncSetAttribute(h_kernel, cudaFuncAttributeMaxDynamicSharedMemorySize, smem);
    cudaFuncSetAttribute(z_kernel, cudaFuncAttributeMaxDynamicSharedMemorySize, smem);
    cudaFuncSetAttribute(y_kernel, cudaFuncAttributeMaxDynamicSharedMemorySize, smem);

    twiddle_kernel<<<(NFFT + NT - 1) / NT, NT>>>();
    h_kernel<<<NPART, NT, smem>>>(ir);
    z_kernel<<<dim3(NBLK, PAIRS), NT, smem>>>(x);
    y_kernel<<<dim3(NBLK, PAIRS), NT, smem>>>(x, wp, out);
}

// round 7
// speedup vs baseline: 2.1930x; 1.6375x over previous
#include <cuda_runtime.h>
#include <math.h>

// ---------------------------------------------------------------------------
// Frequency-domain partitioned convolution (uniform overlap-save), v3.
//   v2 + twiddles computed on the fly with __sincosf (MUFU) instead of a
//   128KB gmem table (which thrashed L1). Register-staged radix-16 passes,
//   1024 threads/CTA, padded smem. Forward DIF leaves digit-reversed order;
//   H stored in same order; exact algebraic inverse; 1/N folded into H.
// ---------------------------------------------------------------------------

#define T_LEN   441000
#define PAIRS   16
#define IR_LEN  44100
#define P_HOP   8192
#define NFFT    16384
#define NBLK    54          // ceil(441000 / 8192)
#define NPART   6           // ceil(44100 / 8192)
#define NT      1024

__device__ __align__(16) float2 g_H[NPART][NFFT];
__device__ __align__(16) float2 g_Z[PAIRS][NBLK][NFFT];

__device__ __forceinline__ int PADi(int i) { return i + (i >> 4); }
#define SMEM_F2 (NFFT + (NFFT >> 4))        // padded float2 count

// ---------------- complex helpers ----------------
__device__ __forceinline__ float2 cadd(float2 a, float2 b) { return make_float2(a.x + b.x, a.y + b.y); }
__device__ __forceinline__ float2 csub(float2 a, float2 b) { return make_float2(a.x - b.x, a.y - b.y); }
__device__ __forceinline__ float2 cmul(float2 a, float2 b) {
    return make_float2(fmaf(a.x, b.x, -a.y * b.y), fmaf(a.x, b.y, a.y * b.x));
}
// a * conj(b)
__device__ __forceinline__ float2 cmulc(float2 a, float2 b) {
    return make_float2(fmaf(a.x, b.x, a.y * b.y), fmaf(a.y, b.x, -a.x * b.y));
}
__device__ __forceinline__ float2 sincosw(float ang) {
    float2 w; __sincosf(ang, &w.y, &w.x); return w;   // w = (cos, sin)
}
__device__ __forceinline__ void tw_pow(float2 w1, float2& w2, float2& w3) {
    w2 = cmul(w1, w1); w3 = cmul(w2, w1);
}

// ---------------- radix-4 butterflies ----------------
__device__ __forceinline__ void bfly_fwd_w(float2& a, float2& b, float2& c, float2& d,
                                           float2 w1, float2 w2, float2 w3) {
    float2 u0 = cadd(a, c), u1 = csub(a, c), u2 = cadd(b, d), t = csub(b, d);
    float2 u3 = make_float2(t.y, -t.x);   // -i*(b-d)
    a = cadd(u0, u2);
    b = cmul(cadd(u1, u3), w1);
    c = cmul(csub(u0, u2), w2);
    d = cmul(csub(u1, u3), w3);
}
__device__ __forceinline__ void bfly_fwd_nw(float2& a, float2& b, float2& c, float2& d) {
    float2 u0 = cadd(a, c), u1 = csub(a, c), u2 = cadd(b, d), t = csub(b, d);
    float2 u3 = make_float2(t.y, -t.x);
    a = cadd(u0, u2); b = cadd(u1, u3); c = csub(u0, u2); d = csub(u1, u3);
}
__device__ __forceinline__ void bfly_inv_w(float2& a, float2& b, float2& c, float2& d,
                                           float2 w1, float2 w2, float2 w3) {
    float2 y0 = a, y1 = cmulc(b, w1), y2 = cmulc(c, w2), y3 = cmulc(d, w3);
    float2 v0 = cadd(y0, y2), v2 = csub(y0, y2);
    float2 v1 = cadd(y1, y3), v3 = csub(y1, y3);
    float2 iv3 = make_float2(-v3.y, v3.x);  // i*v3
    a = cadd(v0, v1); b = cadd(v2, iv3); c = csub(v0, v1); d = csub(v2, iv3);
}
__device__ __forceinline__ void bfly_inv_nw(float2& a, float2& b, float2& c, float2& d) {
    float2 v0 = cadd(a, c), v2 = csub(a, c);
    float2 v1 = cadd(b, d), v3 = csub(b, d);
    float2 iv3 = make_float2(-v3.y, v3.x);
    a = cadd(v0, v1); b = cadd(v2, iv3); c = csub(v0, v1); d = csub(v2, iv3);
}

// ---------------- register pass: stages S and S+1 ----------------
// Thread t owns v[j] = element base + j*mq, mq = m/4, m = 4^(6-S).
// Twiddle for sub-column j1: angle c*(r + j1*mq), c = -2*pi*4^S / N.
// Shared (second-stage) twiddle: angle 4*c*r.  All |angles| < pi/2*1.01.
template<int S>
__device__ __forceinline__ void fwd_bflys(float2 v[16], int r, int mq) {
    const float c = (-6.283185307179586f / (float)NFFT) * (float)(1 << (2 * S));
    float2 w1  = sincosw(c * (float)r);
    float2 rot = sincosw(c * (float)mq);
    #pragma unroll
    for (int j1 = 0; j1 < 4; ++j1) {
        float2 w2, w3; tw_pow(w1, w2, w3);
        bfly_fwd_w(v[j1], v[j1 + 4], v[j1 + 8], v[j1 + 12], w1, w2, w3);
        if (j1 < 3) w1 = cmul(w1, rot);
    }
    float2 s1 = sincosw(4.0f * c * (float)r);
    float2 s2, s3; tw_pow(s1, s2, s3);
    #pragma unroll
    for (int q = 0; q < 4; ++q)
        bfly_fwd_w(v[4 * q], v[4 * q + 1], v[4 * q + 2], v[4 * q + 3], s1, s2, s3);
}

template<int S>
__device__ __forceinline__ void inv_bflys(float2 v[16], int r, int mq) {
    const float c = (-6.283185307179586f / (float)NFFT) * (float)(1 << (2 * S));
    float2 s1 = sincosw(4.0f * c * (float)r);
    float2 s2, s3; tw_pow(s1, s2, s3);
    #pragma unroll
    for (int q = 0; q < 4; ++q)
        bfly_inv_w(v[4 * q], v[4 * q + 1], v[4 * q + 2], v[4 * q + 3], s1, s2, s3);
    float2 w1  = sincosw(c * (float)r);
    float2 rot = sincosw(c * (float)mq);
    #pragma unroll
    for (int j1 = 0; j1 < 4; ++j1) {
        float2 w2, w3; tw_pow(w1, w2, w3);
        bfly_inv_w(v[j1], v[j1 + 4], v[j1 + 8], v[j1 + 12], w1, w2, w3);
        if (j1 < 3) w1 = cmul(w1, rot);
    }
}

template<int S>
__device__ __forceinline__ void fwd_mid_pass(float2* sm, int t) {
    const int m   = 1 << (12 - 2 * S);
    const int mq  = m >> 2;
    const int r    = t & (mq - 1);
    const int base = ((t >> (10 - 2 * S)) << (14 - 2 * S)) + r;
    float2 v[16];
    #pragma unroll
    for (int j = 0; j < 16; ++j) v[j] = sm[PADi(base + j * mq)];
    fwd_bflys<S>(v, r, mq);
    #pragma unroll
    for (int j = 0; j < 16; ++j) sm[PADi(base + j * mq)] = v[j];
}

__device__ __forceinline__ void fwd_pass0_store(float2* sm, int t, float2 v[16]) {
    fwd_bflys<0>(v, t, 1024);
    #pragma unroll
    for (int j = 0; j < 16; ++j) sm[PADi(t + j * 1024)] = v[j];
}

// Forward stage 6 (unity twiddles, contiguous quads) + store to global (scaled).
__device__ __forceinline__ void fwd_stage6_store(const float2* sm, int t,
                                                 float2* __restrict__ dst, float s) {
    float4* dst4 = (float4*)dst;
    #pragma unroll
    for (int u = 0; u < 4; ++u) {
        int a = 4 * t + 4096 * u;
        float2 va = sm[PADi(a)], vb = sm[PADi(a + 1)];
        float2 vc = sm[PADi(a + 2)], vd = sm[PADi(a + 3)];
        bfly_fwd_nw(va, vb, vc, vd);
        dst4[(a >> 1)]     = make_float4(va.x * s, va.y * s, vb.x * s, vb.y * s);
        dst4[(a >> 1) + 1] = make_float4(vc.x * s, vc.y * s, vd.x * s, vd.y * s);
    }
}

__device__ __forceinline__ void inv_stage6(float2* sm, int t) {
    #pragma unroll
    for (int u = 0; u < 4; ++u) {
        int a = 4 * t + 4096 * u;
        float2 va = sm[PADi(a)], vb = sm[PADi(a + 1)];
        float2 vc = sm[PADi(a + 2)], vd = sm[PADi(a + 3)];
        bfly_inv_nw(va, vb, vc, vd);
        sm[PADi(a)] = va; sm[PADi(a + 1)] = vb;
        sm[PADi(a + 2)] = vc; sm[PADi(a + 3)] = vd;
    }
}

template<int S>
__device__ __forceinline__ void inv_mid_pass(float2* sm, int t) {
    const int m   = 1 << (12 - 2 * S);
    const int mq  = m >> 2;
    const int r    = t & (mq - 1);
    const int base = ((t >> (10 - 2 * S)) << (14 - 2 * S)) + r;
    float2 v[16];
    #pragma unroll
    for (int j = 0; j < 16; ++j) v[j] = sm[PADi(base + j * mq)];
    inv_bflys<S>(v, r, mq);
    #pragma unroll
    for (int j = 0; j < 16; ++j) sm[PADi(base + j * mq)] = v[j];
}

// ---------------- kernels ----------------
__global__ void __launch_bounds__(NT, 1) h_kernel(const float* __restrict__ ir) {
    extern __shared__ float2 sm[];
    const int c   = blockIdx.x;
    const int t   = threadIdx.x;
    float2 v[16];
    #pragma unroll
    for (int j = 0; j < 16; ++j) {
        int k = t + 1024 * j;
        int tap = c * P_HOP + k;
        float val = (k < P_HOP && tap < IR_LEN) ? ir[tap] : 0.0f;
        v[j] = make_float2(val, 0.0f);
    }
    fwd_pass0_store(sm, t, v);
    __syncthreads();
    fwd_mid_pass<2>(sm, t);
    __syncthreads();
    fwd_mid_pass<4>(sm, t);
    __syncthreads();
    fwd_stage6_store(sm, t, g_H[c], 1.0f / (float)NFFT);
}

__global__ void __launch_bounds__(NT, 1) z_kernel(const float* __restrict__ x) {
    extern __shared__ float2 sm[];
    const int d = blockIdx.x;     // input block index
    const int p = blockIdx.y;     // batch pair
    const int t = threadIdx.x;
    const int base = d * P_HOP - P_HOP;   // covers [(d-1)P, (d+1)P)
    const float* xe = x + (2 * p)     * T_LEN;
    const float* xo = x + (2 * p + 1) * T_LEN;
    float2 v[16];
    #pragma unroll
    for (int j = 0; j < 16; ++j) {
        int idx = base + t + 1024 * j;
        float re = 0.0f, im = 0.0f;
        if (idx >= 0 && idx < T_LEN) { re = xe[idx]; im = xo[idx]; }
        v[j] = make_float2(re, im);
    }
    fwd_pass0_store(sm, t, v);
    __syncthreads();
    fwd_mid_pass<2>(sm, t);
    __syncthreads();
    fwd_mid_pass<4>(sm, t);
    __syncthreads();
    fwd_stage6_store(sm, t, g_Z[p][d], 1.0f);
}

// Spectral MAC body: NCP partitions (compile-time when FULL).
template<bool FULL>
__device__ __forceinline__ void mac_phase(float2* sm, int t, int mBlk, int p, int ncp) {
    #pragma unroll
    for (int j = 0; j < 8; ++j) {
        int kq = t + 1024 * j;              // float4 index -> complex 2kq, 2kq+1
        float2 a0 = make_float2(0.0f, 0.0f);
        float2 a1 = make_float2(0.0f, 0.0f);
        if (FULL) {
            #pragma unroll
            for (int c = 0; c < NPART; ++c) {
                float4 h = __ldg((const float4*)g_H[c] + kq);
                float4 z = __ldg((const float4*)g_Z[p][mBlk - c] + kq);
                a0 = cadd(a0, cmul(make_float2(h.x, h.y), make_float2(z.x, z.y)));
                a1 = cadd(a1, cmul(make_float2(h.z, h.w), make_float2(z.z, z.w)));
            }
        } else {
            for (int c = 0; c < ncp; ++c) {
                float4 h = __ldg((const float4*)g_H[c] + kq);
                float4 z = __ldg((const float4*)g_Z[p][mBlk - c] + kq);
                a0 = cadd(a0, cmul(make_float2(h.x, h.y), make_float2(z.x, z.y)));
                a1 = cadd(a1, cmul(make_float2(h.z, h.w), make_float2(z.z, z.w)));
            }
        }
        sm[PADi(2 * kq)]     = a0;
        sm[PADi(2 * kq + 1)] = a1;
    }
}

__global__ void __launch_bounds__(NT, 1) y_kernel(const float* __restrict__ x,
                                                  const float* __restrict__ wet_param,
                                                  float* __restrict__ out) {
    extern __shared__ float2 sm[];
    const int mBlk = blockIdx.x;  // output block index
    const int p    = blockIdx.y;  // batch pair
    const int t    = threadIdx.x;

    if (mBlk >= NPART - 1) mac_phase<true >(sm, t, mBlk, p, NPART);
    else                   mac_phase<false>(sm, t, mBlk, p, mBlk + 1);
    __syncthreads();

    inv_stage6(sm, t);
    __syncthreads();
    inv_mid_pass<4>(sm, t);     // stages 5 then 4
    __syncthreads();
    inv_mid_pass<2>(sm, t);     // stages 3 then 2
    __syncthreads();

    // Final inverse pass: stages 1 then 0 in registers, then write output mix.
    float2 v[16];
    #pragma unroll
    for (int j = 0; j < 16; ++j) v[j] = sm[PADi(t + 1024 * j)];
    inv_bflys<0>(v, t, 1024);

    const float wet = 1.0f / (1.0f + __expf(-wet_param[0]));
    const float dry = 1.0f - wet;
    const float* xe = x + (2 * p)     * T_LEN;
    const float* xo = x + (2 * p + 1) * T_LEN;
    float* oe = out + (2 * p)     * T_LEN;
    float* oo = out + (2 * p + 1) * T_LEN;

    // valid overlap-save outputs at natural positions [P, 2P) = j in [8,16)
    #pragma unroll
    for (int j = 8; j < 16; ++j) {
        int n = mBlk * P_HOP + t + 1024 * j - P_HOP;
        if (n < T_LEN) {
            oe[n] = fmaf(dry, xe[n], wet * v[j].x);
            oo[n] = fmaf(dry, xo[n], wet * v[j].y);
        }
    }
}

// ---------------- launcher ----------------
extern "C" void kernel_launch(void* const* d_in, const int* in_sizes, int n_in,
                              void* d_out, int out_size) {
    const float* x  = (const float*)d_in[0];
    const float* ir = (const float*)d_in[1];
    const float* wp = (const float*)d_in[2];
    float* out = (float*)d_out;

    const int smem = SMEM_F2 * sizeof(float2);   // 139264 B
    cudaFuncSetAttribute(h_kernel, cudaFuncAttributeMaxDynamicSharedMemorySize, smem);
    cudaFuncSetAttribute(z_kernel, cudaFuncAttributeMaxDynamicSharedMemorySize, smem);
    cudaFuncSetAttribute(y_kernel, cudaFuncAttributeMaxDynamicSharedMemorySize, smem);

    h_kernel<<<NPART, NT, smem>>>(ir);
    z_kernel<<<dim3(NBLK, PAIRS), NT, smem>>>(x);
    y_kernel<<<dim3(NBLK, PAIRS), NT, smem>>>(x, wp, out);
}